// round 1
// baseline (speedup 1.0000x reference)
#include <cuda_runtime.h>
#include <cuda_bf16.h>
#include <math.h>

// ---------------------------------------------------------------------------
// Problem constants (fixed by the reference)
// ---------------------------------------------------------------------------
#define B_    16
#define Hh    56
#define Ww    56
#define Nn    3136          // H*W
#define C_    384
#define C3    1152          // 3*C
#define HEADS_ 12
#define HD    32            // head dim
#define WS_   7
#define WT    49            // tokens per window
#define WG    8             // windows per row (56/7)
#define NW    64            // windows per image
#define M_ROWS (B_*Nn)      // 50176

// Scratch (allocation-free rule: __device__ globals)
__device__ float g_qkv[(size_t)M_ROWS * C3];   // (B*N, 3C)  q|k|v
__device__ float g_y  [(size_t)M_ROWS * C_];   // attention out + LIM

// ---------------------------------------------------------------------------
// Tiled fp32 SGEMM: C[M,N] = A[M,K] @ B[K,N] (+ bias[N])
// BM=BN=128, BK=8, 256 threads, 8x8 micro-tile. All dims divide exactly.
// ---------------------------------------------------------------------------
__global__ __launch_bounds__(256)
void sgemm_kernel(const float* __restrict__ A, const float* __restrict__ B,
                  float* __restrict__ C, int M, int N, int K,
                  const float* __restrict__ bias)
{
    const int BM = 128, BN = 128, BK = 8;
    __shared__ float As[BK][BM];
    __shared__ float Bs[BK][BN];

    int tid = threadIdx.x;
    int bx = blockIdx.x;          // N tile
    int by = blockIdx.y;          // M tile
    int tx = tid & 15;            // 0..15
    int ty = tid >> 4;            // 0..15

    const float* Ab = A + (size_t)by * BM * K;
    const float* Bb = B + (size_t)bx * BN;

    // A stage: 128 rows x 8 k, one float4 per thread
    int a_row = tid >> 1;
    int a_col = (tid & 1) * 4;
    // B stage: 8 rows x 128 cols, one float4 per thread
    int b_row = tid >> 5;
    int b_col = (tid & 31) * 4;

    float acc[8][8];
#pragma unroll
    for (int i = 0; i < 8; i++)
#pragma unroll
        for (int j = 0; j < 8; j++) acc[i][j] = 0.f;

    for (int k0 = 0; k0 < K; k0 += BK) {
        float4 av = *reinterpret_cast<const float4*>(Ab + (size_t)a_row * K + k0 + a_col);
        As[a_col + 0][a_row] = av.x;
        As[a_col + 1][a_row] = av.y;
        As[a_col + 2][a_row] = av.z;
        As[a_col + 3][a_row] = av.w;
        float4 bv = *reinterpret_cast<const float4*>(Bb + (size_t)(k0 + b_row) * N + b_col);
        *reinterpret_cast<float4*>(&Bs[b_row][b_col]) = bv;
        __syncthreads();

#pragma unroll
        for (int k = 0; k < BK; k++) {
            float a[8], b[8];
            float4 a0 = *reinterpret_cast<const float4*>(&As[k][ty * 8]);
            float4 a1 = *reinterpret_cast<const float4*>(&As[k][ty * 8 + 4]);
            a[0]=a0.x; a[1]=a0.y; a[2]=a0.z; a[3]=a0.w;
            a[4]=a1.x; a[5]=a1.y; a[6]=a1.z; a[7]=a1.w;
            float4 b0 = *reinterpret_cast<const float4*>(&Bs[k][tx * 8]);
            float4 b1 = *reinterpret_cast<const float4*>(&Bs[k][tx * 8 + 4]);
            b[0]=b0.x; b[1]=b0.y; b[2]=b0.z; b[3]=b0.w;
            b[4]=b1.x; b[5]=b1.y; b[6]=b1.z; b[7]=b1.w;
#pragma unroll
            for (int i = 0; i < 8; i++)
#pragma unroll
                for (int j = 0; j < 8; j++)
                    acc[i][j] = fmaf(a[i], b[j], acc[i][j]);
        }
        __syncthreads();
    }

    float badd[8];
#pragma unroll
    for (int j = 0; j < 8; j++)
        badd[j] = bias ? bias[(size_t)bx * BN + tx * 8 + j] : 0.f;

#pragma unroll
    for (int i = 0; i < 8; i++) {
        size_t row = (size_t)by * BM + ty * 8 + i;
        float* Cp = C + row * N + (size_t)bx * BN + tx * 8;
        float4 o0, o1;
        o0.x = acc[i][0] + badd[0]; o0.y = acc[i][1] + badd[1];
        o0.z = acc[i][2] + badd[2]; o0.w = acc[i][3] + badd[3];
        o1.x = acc[i][4] + badd[4]; o1.y = acc[i][5] + badd[5];
        o1.z = acc[i][6] + badd[6]; o1.w = acc[i][7] + badd[7];
        *reinterpret_cast<float4*>(Cp)     = o0;
        *reinterpret_cast<float4*>(Cp + 4) = o1;
    }
}

// ---------------------------------------------------------------------------
// Window attention: one block per (batch, window, head), 64 threads.
// Thread t < 49 owns query row t.
// ---------------------------------------------------------------------------
__global__ __launch_bounds__(64)
void attn_kernel(const float* __restrict__ qkv, float* __restrict__ y)
{
    int blk  = blockIdx.x;
    int head = blk % HEADS_;
    int w    = (blk / HEADS_) % NW;
    int b    = blk / (HEADS_ * NW);
    int wy = w / WG, wx = w % WG;

    __shared__ float ks[WT][HD];
    __shared__ float vs[WT][HD];

    int tid = threadIdx.x;
    for (int idx = tid; idx < WT * HD; idx += 64) {
        int j = idx / HD, d = idx % HD;
        int n = (wy * WS_ + j / WS_) * Ww + wx * WS_ + (j % WS_);
        size_t base = ((size_t)b * Nn + n) * C3 + head * HD + d;
        ks[j][d] = qkv[base + C_];
        vs[j][d] = qkv[base + 2 * C_];
    }
    __syncthreads();

    if (tid >= WT) return;
    int n = (wy * WS_ + tid / WS_) * Ww + wx * WS_ + (tid % WS_);
    const float* qp = qkv + ((size_t)b * Nn + n) * C3 + head * HD;

    float q[HD];
#pragma unroll
    for (int d = 0; d < HD; d++) q[d] = qp[d];

    const float scale = 0.1767766952966369f;  // 1/sqrt(32)
    float s[WT];
    float mx = -1e30f;
#pragma unroll 7
    for (int j = 0; j < WT; j++) {
        float acc = 0.f;
#pragma unroll
        for (int d = 0; d < HD; d++) acc = fmaf(q[d], ks[j][d], acc);
        acc *= scale;
        s[j] = acc;
        mx = fmaxf(mx, acc);
    }
    float sum = 0.f;
#pragma unroll 7
    for (int j = 0; j < WT; j++) { s[j] = __expf(s[j] - mx); sum += s[j]; }
    float inv = 1.f / sum;

    float o[HD];
#pragma unroll
    for (int d = 0; d < HD; d++) o[d] = 0.f;
#pragma unroll 7
    for (int j = 0; j < WT; j++) {
        float p = s[j];
#pragma unroll
        for (int d = 0; d < HD; d++) o[d] = fmaf(p, vs[j][d], o[d]);
    }

    float* yp = y + ((size_t)b * Nn + n) * C_ + head * HD;
#pragma unroll
    for (int d = 0; d < HD; d++) yp[d] = o[d] * inv;
}

// ---------------------------------------------------------------------------
// Depthwise 3x3 conv (SAME) over v, accumulated into y.
// One thread per (b, n, c) output element; adjacent threads -> adjacent c.
// ---------------------------------------------------------------------------
__global__ __launch_bounds__(256)
void conv_add_kernel(const float* __restrict__ qkv, const float* __restrict__ wconv,
                     const float* __restrict__ bconv, float* __restrict__ y)
{
    long long idx = (long long)blockIdx.x * blockDim.x + threadIdx.x;
    if (idx >= (long long)B_ * Nn * C_) return;
    int c = (int)(idx % C_);
    int n = (int)((idx / C_) % Nn);
    int b = (int)(idx / ((long long)C_ * Nn));
    int h = n / Ww, w = n % Ww;

    float acc = bconv[c];
#pragma unroll
    for (int ky = 0; ky < 3; ky++) {
        int hy = h + ky - 1;
        if (hy < 0 || hy >= Hh) continue;
#pragma unroll
        for (int kx = 0; kx < 3; kx++) {
            int wx2 = w + kx - 1;
            if (wx2 < 0 || wx2 >= Ww) continue;
            float vv = qkv[((size_t)b * Nn + hy * Ww + wx2) * C3 + 2 * C_ + c];
            acc = fmaf(vv, wconv[(ky * 3 + kx) * C_ + c], acc);
        }
    }
    y[idx] += acc;
}

// ---------------------------------------------------------------------------
// Launch
// ---------------------------------------------------------------------------
extern "C" void kernel_launch(void* const* d_in, const int* in_sizes, int n_in,
                              void* d_out, int out_size)
{
    const float* x      = (const float*)d_in[0];   // (B, N, C)
    const float* w_qkv  = (const float*)d_in[1];   // (C, 3C)
    const float* w_proj = (const float*)d_in[2];   // (C, C)
    const float* b_proj = (const float*)d_in[3];   // (C,)
    const float* w_conv = (const float*)d_in[4];   // (3,3,1,C)
    const float* b_conv = (const float*)d_in[5];   // (C,)
    float* out = (float*)d_out;                    // (B, N, C)

    float* qkv;  cudaGetSymbolAddress((void**)&qkv, g_qkv);
    float* y;    cudaGetSymbolAddress((void**)&y,   g_y);

    // 1) QKV GEMM: (50176,384) @ (384,1152)
    {
        dim3 grid(C3 / 128, M_ROWS / 128);
        sgemm_kernel<<<grid, 256>>>(x, w_qkv, qkv, M_ROWS, C3, C_, nullptr);
    }
    // 2) window attention -> y
    {
        attn_kernel<<<B_ * NW * HEADS_, 64>>>(qkv, y);
    }
    // 3) depthwise conv LIM branch, += into y
    {
        long long total = (long long)B_ * Nn * C_;
        int blocks = (int)((total + 255) / 256);
        conv_add_kernel<<<blocks, 256>>>(qkv, w_conv, b_conv, y);
    }
    // 4) proj GEMM: (50176,384) @ (384,384) + bias -> out
    {
        dim3 grid(C_ / 128, M_ROWS / 128);
        sgemm_kernel<<<grid, 256>>>(y, w_proj, out, M_ROWS, C_, C_, b_proj);
    }
}

// round 3
// speedup vs baseline: 1.7951x; 1.7951x over previous
#include <cuda_runtime.h>
#include <cuda_bf16.h>
#include <cstdint>
#include <math.h>

// ---------------------------------------------------------------------------
// Problem constants
// ---------------------------------------------------------------------------
#define B_    16
#define Hh    56
#define Ww    56
#define Nn    3136
#define C_    384
#define C3    1152
#define HEADS_ 12
#define HD    32
#define WS_   7
#define WT    49
#define WG    8
#define NW    64
#define M_ROWS (B_*Nn)      // 50176

// ---------------------------------------------------------------------------
// Scratch (__device__ globals; no allocations allowed)
// ---------------------------------------------------------------------------
__device__ float g_qkv[(size_t)M_ROWS * C3];   // fp32 q|k|v
__device__ float g_y  [(size_t)M_ROWS * C_];   // attn out + LIM (fp32)
__device__ __nv_bfloat16 g_xh[(size_t)M_ROWS * C_];
__device__ __nv_bfloat16 g_xl[(size_t)M_ROWS * C_];
__device__ __nv_bfloat16 g_yh[(size_t)M_ROWS * C_];
__device__ __nv_bfloat16 g_yl[(size_t)M_ROWS * C_];
__device__ __nv_bfloat16 g_wqh[C_ * C3];
__device__ __nv_bfloat16 g_wql[C_ * C3];
__device__ __nv_bfloat16 g_wph[C_ * C_];
__device__ __nv_bfloat16 g_wpl[C_ * C_];

// ---------------------------------------------------------------------------
// fp32 -> (bf16 hi, bf16 lo) split.  n must be divisible by 4.
// ---------------------------------------------------------------------------
__global__ __launch_bounds__(256)
void split_kernel(const float* __restrict__ in, __nv_bfloat16* __restrict__ hi,
                  __nv_bfloat16* __restrict__ lo, long long n4)
{
    long long i = (long long)blockIdx.x * blockDim.x + threadIdx.x;
    if (i >= n4) return;
    float4 v = reinterpret_cast<const float4*>(in)[i];
    union { __nv_bfloat16 b[4]; uint2 u; } h, l;
    float f[4] = {v.x, v.y, v.z, v.w};
#pragma unroll
    for (int j = 0; j < 4; j++) {
        __nv_bfloat16 hb = __float2bfloat16(f[j]);
        h.b[j] = hb;
        l.b[j] = __float2bfloat16(f[j] - __bfloat162float(hb));
    }
    reinterpret_cast<uint2*>(hi)[i] = h.u;
    reinterpret_cast<uint2*>(lo)[i] = l.u;
}

// ---------------------------------------------------------------------------
// mma.sync helpers
// ---------------------------------------------------------------------------
__device__ __forceinline__ uint32_t smaddr(const void* p) {
    return (uint32_t)__cvta_generic_to_shared(p);
}
__device__ __forceinline__ void ldsm4(uint32_t* r, uint32_t addr) {
    asm volatile("ldmatrix.sync.aligned.m8n8.x4.shared.b16 {%0,%1,%2,%3}, [%4];\n"
                 : "=r"(r[0]), "=r"(r[1]), "=r"(r[2]), "=r"(r[3]) : "r"(addr));
}
__device__ __forceinline__ void ldsm4t(uint32_t* r, uint32_t addr) {
    asm volatile("ldmatrix.sync.aligned.m8n8.x4.trans.shared.b16 {%0,%1,%2,%3}, [%4];\n"
                 : "=r"(r[0]), "=r"(r[1]), "=r"(r[2]), "=r"(r[3]) : "r"(addr));
}
__device__ __forceinline__ void mma_bf16(float* c, const uint32_t* a,
                                         uint32_t b0, uint32_t b1) {
    asm volatile(
        "mma.sync.aligned.m16n8k16.row.col.f32.bf16.bf16.f32 "
        "{%0,%1,%2,%3}, {%4,%5,%6,%7}, {%8,%9}, {%0,%1,%2,%3};\n"
        : "+f"(c[0]), "+f"(c[1]), "+f"(c[2]), "+f"(c[3])
        : "r"(a[0]), "r"(a[1]), "r"(a[2]), "r"(a[3]), "r"(b0), "r"(b1));
}

// ---------------------------------------------------------------------------
// bf16 split GEMM: C[M,N] = (Ah+Al)[M,K] @ (Bh+Bl)[K,N] (+ bias)
//   = Ah*Bh + Al*Bh + Ah*Bl   (Al*Bl dropped, ~2^-16 relative)
// Block tile 128x128x32, 8 warps, warp tile 32x64 via m16n8k16.
// ---------------------------------------------------------------------------
__global__ __launch_bounds__(256)
void bmma_gemm(const __nv_bfloat16* __restrict__ Ah, const __nv_bfloat16* __restrict__ Al,
               const __nv_bfloat16* __restrict__ Bh, const __nv_bfloat16* __restrict__ Bl,
               float* __restrict__ C, int M, int N, int K,
               const float* __restrict__ bias)
{
    __shared__ __align__(16) __nv_bfloat16 sAh[128][40];
    __shared__ __align__(16) __nv_bfloat16 sAl[128][40];
    __shared__ __align__(16) __nv_bfloat16 sBh[32][136];
    __shared__ __align__(16) __nv_bfloat16 sBl[32][136];

    const int tid  = threadIdx.x;
    const int lane = tid & 31;
    const int warp = tid >> 5;
    const int wm = (warp & 3) * 32;   // warp row offset in tile
    const int wn = (warp >> 2) * 64;  // warp col offset in tile
    const int bx = blockIdx.x, by = blockIdx.y;

    const __nv_bfloat16* Agh = Ah + (size_t)by * 128 * K;
    const __nv_bfloat16* Agl = Al + (size_t)by * 128 * K;
    const __nv_bfloat16* Bgh = Bh + (size_t)bx * 128;
    const __nv_bfloat16* Bgl = Bl + (size_t)bx * 128;

    uint4 rah[2], ral[2], rbh[2], rbl[2];
    const int ntiles = K / 32;

    // --- preload tile 0 ---
    {
        int k0 = 0;
#pragma unroll
        for (int i = 0; i < 2; i++) {
            int seg = tid + i * 256;
            int ar = seg >> 2, ac = (seg & 3) * 8;
            rah[i] = *reinterpret_cast<const uint4*>(Agh + (size_t)ar * K + k0 + ac);
            ral[i] = *reinterpret_cast<const uint4*>(Agl + (size_t)ar * K + k0 + ac);
            int br = seg >> 4, bc = (seg & 15) * 8;
            rbh[i] = *reinterpret_cast<const uint4*>(Bgh + (size_t)(k0 + br) * N + bc);
            rbl[i] = *reinterpret_cast<const uint4*>(Bgl + (size_t)(k0 + br) * N + bc);
        }
    }

    float acc[2][8][4];
#pragma unroll
    for (int mt = 0; mt < 2; mt++)
#pragma unroll
        for (int nt = 0; nt < 8; nt++)
#pragma unroll
            for (int j = 0; j < 4; j++) acc[mt][nt][j] = 0.f;

    for (int kt = 0; kt < ntiles; kt++) {
#pragma unroll
        for (int i = 0; i < 2; i++) {
            int seg = tid + i * 256;
            int ar = seg >> 2, ac = (seg & 3) * 8;
            *reinterpret_cast<uint4*>(&sAh[ar][ac]) = rah[i];
            *reinterpret_cast<uint4*>(&sAl[ar][ac]) = ral[i];
            int br = seg >> 4, bc = (seg & 15) * 8;
            *reinterpret_cast<uint4*>(&sBh[br][bc]) = rbh[i];
            *reinterpret_cast<uint4*>(&sBl[br][bc]) = rbl[i];
        }
        __syncthreads();

        if (kt + 1 < ntiles) {
            int k0 = (kt + 1) * 32;
#pragma unroll
            for (int i = 0; i < 2; i++) {
                int seg = tid + i * 256;
                int ar = seg >> 2, ac = (seg & 3) * 8;
                rah[i] = *reinterpret_cast<const uint4*>(Agh + (size_t)ar * K + k0 + ac);
                ral[i] = *reinterpret_cast<const uint4*>(Agl + (size_t)ar * K + k0 + ac);
                int br = seg >> 4, bc = (seg & 15) * 8;
                rbh[i] = *reinterpret_cast<const uint4*>(Bgh + (size_t)(k0 + br) * N + bc);
                rbl[i] = *reinterpret_cast<const uint4*>(Bgl + (size_t)(k0 + br) * N + bc);
            }
        }

#pragma unroll
        for (int ks = 0; ks < 2; ks++) {
            const int kk = ks * 16;
            uint32_t ah[2][4], al[2][4];
#pragma unroll
            for (int mt = 0; mt < 2; mt++) {
                int row = wm + mt * 16 + (lane & 15);
                int col = kk + ((lane >> 4) << 3);
                ldsm4(ah[mt], smaddr(&sAh[row][col]));
                ldsm4(al[mt], smaddr(&sAl[row][col]));
            }
            uint32_t bh[4][4], bl[4][4];
#pragma unroll
            for (int nt = 0; nt < 4; nt++) {
                int row = kk + (lane & 15);
                int col = wn + nt * 16 + ((lane >> 4) << 3);
                ldsm4t(bh[nt], smaddr(&sBh[row][col]));
                ldsm4t(bl[nt], smaddr(&sBl[row][col]));
            }
#pragma unroll
            for (int mt = 0; mt < 2; mt++)
#pragma unroll
                for (int nt = 0; nt < 8; nt++) {
                    uint32_t h0 = bh[nt >> 1][(nt & 1) * 2];
                    uint32_t h1 = bh[nt >> 1][(nt & 1) * 2 + 1];
                    uint32_t l0 = bl[nt >> 1][(nt & 1) * 2];
                    uint32_t l1 = bl[nt >> 1][(nt & 1) * 2 + 1];
                    mma_bf16(acc[mt][nt], ah[mt], h0, h1);   // Ah*Bh
                    mma_bf16(acc[mt][nt], al[mt], h0, h1);   // Al*Bh
                    mma_bf16(acc[mt][nt], ah[mt], l0, l1);   // Ah*Bl
                }
        }
        __syncthreads();
    }

#pragma unroll
    for (int mt = 0; mt < 2; mt++) {
        int r0 = by * 128 + wm + mt * 16 + (lane >> 2);
#pragma unroll
        for (int nt = 0; nt < 8; nt++) {
            int c0 = bx * 128 + wn + nt * 8 + (lane & 3) * 2;
            float bb0 = bias ? bias[c0] : 0.f;
            float bb1 = bias ? bias[c0 + 1] : 0.f;
            float2 v0 = {acc[mt][nt][0] + bb0, acc[mt][nt][1] + bb1};
            float2 v1 = {acc[mt][nt][2] + bb0, acc[mt][nt][3] + bb1};
            *reinterpret_cast<float2*>(&C[(size_t)r0 * N + c0]) = v0;
            *reinterpret_cast<float2*>(&C[(size_t)(r0 + 8) * N + c0]) = v1;
        }
    }
}

// ---------------------------------------------------------------------------
// Window attention: one block per (batch, window, head), 64 threads.
// ---------------------------------------------------------------------------
__global__ __launch_bounds__(64)
void attn_kernel(const float* __restrict__ qkv, float* __restrict__ y)
{
    int blk  = blockIdx.x;
    int head = blk % HEADS_;
    int w    = (blk / HEADS_) % NW;
    int b    = blk / (HEADS_ * NW);
    int wy = w / WG, wx = w % WG;

    __shared__ float ks[WT][HD];
    __shared__ float vs[WT][HD];

    int tid = threadIdx.x;
    for (int idx = tid; idx < WT * HD; idx += 64) {
        int j = idx / HD, d = idx % HD;
        int n = (wy * WS_ + j / WS_) * Ww + wx * WS_ + (j % WS_);
        size_t base = ((size_t)b * Nn + n) * C3 + head * HD + d;
        ks[j][d] = qkv[base + C_];
        vs[j][d] = qkv[base + 2 * C_];
    }
    __syncthreads();

    if (tid >= WT) return;
    int n = (wy * WS_ + tid / WS_) * Ww + wx * WS_ + (tid % WS_);
    const float* qp = qkv + ((size_t)b * Nn + n) * C3 + head * HD;

    float q[HD];
#pragma unroll
    for (int d = 0; d < HD; d++) q[d] = qp[d];

    const float scale = 0.1767766952966369f;
    float s[WT];
    float mx = -1e30f;
#pragma unroll 7
    for (int j = 0; j < WT; j++) {
        float acc = 0.f;
#pragma unroll
        for (int d = 0; d < HD; d++) acc = fmaf(q[d], ks[j][d], acc);
        acc *= scale;
        s[j] = acc;
        mx = fmaxf(mx, acc);
    }
    float sum = 0.f;
#pragma unroll 7
    for (int j = 0; j < WT; j++) { s[j] = __expf(s[j] - mx); sum += s[j]; }
    float inv = 1.f / sum;

    float o[HD];
#pragma unroll
    for (int d = 0; d < HD; d++) o[d] = 0.f;
#pragma unroll 7
    for (int j = 0; j < WT; j++) {
        float p = s[j];
#pragma unroll
        for (int d = 0; d < HD; d++) o[d] = fmaf(p, vs[j][d], o[d]);
    }

    float* yp = y + ((size_t)b * Nn + n) * C_ + head * HD;
#pragma unroll
    for (int d = 0; d < HD; d++) yp[d] = o[d] * inv;
}

// ---------------------------------------------------------------------------
// Depthwise 3x3 conv (SAME) over v, accumulated into y. float4 over channels.
// One thread per (b, n, c4) where c4 indexes groups of 4 channels.
// ---------------------------------------------------------------------------
__global__ __launch_bounds__(256)
void conv_add_kernel(const float* __restrict__ qkv, const float* __restrict__ wconv,
                     const float* __restrict__ bconv, float* __restrict__ y)
{
    const int C4 = C_ / 4;
    long long idx = (long long)blockIdx.x * blockDim.x + threadIdx.x;
    if (idx >= (long long)B_ * Nn * C4) return;
    int c4 = (int)(idx % C4);
    int n  = (int)((idx / C4) % Nn);
    int b  = (int)(idx / ((long long)C4 * Nn));
    int h = n / Ww, w = n % Ww;
    int c = c4 * 4;

    float4 acc = *reinterpret_cast<const float4*>(bconv + c);
#pragma unroll
    for (int ky = 0; ky < 3; ky++) {
        int hy = h + ky - 1;
        if (hy < 0 || hy >= Hh) continue;
#pragma unroll
        for (int kx = 0; kx < 3; kx++) {
            int wx2 = w + kx - 1;
            if (wx2 < 0 || wx2 >= Ww) continue;
            float4 vv = *reinterpret_cast<const float4*>(
                qkv + ((size_t)b * Nn + hy * Ww + wx2) * C3 + 2 * C_ + c);
            float4 wc = *reinterpret_cast<const float4*>(
                wconv + (ky * 3 + kx) * C_ + c);
            acc.x = fmaf(vv.x, wc.x, acc.x);
            acc.y = fmaf(vv.y, wc.y, acc.y);
            acc.z = fmaf(vv.z, wc.z, acc.z);
            acc.w = fmaf(vv.w, wc.w, acc.w);
        }
    }
    float4* yp = reinterpret_cast<float4*>(y + ((size_t)b * Nn + n) * C_ + c);
    float4 old = *yp;
    old.x += acc.x; old.y += acc.y; old.z += acc.z; old.w += acc.w;
    *yp = old;
}

// ---------------------------------------------------------------------------
// Launch
// ---------------------------------------------------------------------------
extern "C" void kernel_launch(void* const* d_in, const int* in_sizes, int n_in,
                              void* d_out, int out_size)
{
    const float* x      = (const float*)d_in[0];
    const float* w_qkv  = (const float*)d_in[1];
    const float* w_proj = (const float*)d_in[2];
    const float* b_proj = (const float*)d_in[3];
    const float* w_conv = (const float*)d_in[4];
    const float* b_conv = (const float*)d_in[5];
    float* out = (float*)d_out;

    float *qkv, *y;
    __nv_bfloat16 *xh, *xl, *yh, *yl, *wqh, *wql, *wph, *wpl;
    cudaGetSymbolAddress((void**)&qkv, g_qkv);
    cudaGetSymbolAddress((void**)&y,   g_y);
    cudaGetSymbolAddress((void**)&xh,  g_xh);
    cudaGetSymbolAddress((void**)&xl,  g_xl);
    cudaGetSymbolAddress((void**)&yh,  g_yh);
    cudaGetSymbolAddress((void**)&yl,  g_yl);
    cudaGetSymbolAddress((void**)&wqh, g_wqh);
    cudaGetSymbolAddress((void**)&wql, g_wql);
    cudaGetSymbolAddress((void**)&wph, g_wph);
    cudaGetSymbolAddress((void**)&wpl, g_wpl);

    // split x, w_qkv, w_proj into bf16 hi/lo
    {
        long long n4 = (long long)M_ROWS * C_ / 4;
        split_kernel<<<(unsigned)((n4 + 255) / 256), 256>>>(x, xh, xl, n4);
        long long w4 = (long long)C_ * C3 / 4;
        split_kernel<<<(unsigned)((w4 + 255) / 256), 256>>>(w_qkv, wqh, wql, w4);
        long long p4 = (long long)C_ * C_ / 4;
        split_kernel<<<(unsigned)((p4 + 255) / 256), 256>>>(w_proj, wph, wpl, p4);
    }
    // 1) QKV GEMM (tensor cores): (50176,384) @ (384,1152)
    {
        dim3 grid(C3 / 128, M_ROWS / 128);
        bmma_gemm<<<grid, 256>>>(xh, xl, wqh, wql, qkv, M_ROWS, C3, C_, nullptr);
    }
    // 2) window attention -> y
    attn_kernel<<<B_ * NW * HEADS_, 64>>>(qkv, y);
    // 3) depthwise conv, += into y
    {
        long long total = (long long)B_ * Nn * (C_ / 4);
        conv_add_kernel<<<(unsigned)((total + 255) / 256), 256>>>(qkv, w_conv, b_conv, y);
    }
    // 4) split y, proj GEMM + bias -> out
    {
        long long n4 = (long long)M_ROWS * C_ / 4;
        split_kernel<<<(unsigned)((n4 + 255) / 256), 256>>>(y, yh, yl, n4);
        dim3 grid(C_ / 128, M_ROWS / 128);
        bmma_gemm<<<grid, 256>>>(yh, yl, wph, wpl, out, M_ROWS, C_, C_, b_proj);
    }
}

// round 4
// speedup vs baseline: 2.1096x; 1.1752x over previous
#include <cuda_runtime.h>
#include <cuda_bf16.h>
#include <cstdint>
#include <math.h>

// ---------------------------------------------------------------------------
// Problem constants
// ---------------------------------------------------------------------------
#define B_    16
#define Hh    56
#define Ww    56
#define Nn    3136
#define C_    384
#define C3    1152
#define HEADS_ 12
#define HD    32
#define WS_   7
#define WT    49
#define WG    8
#define NW    64
#define M_ROWS (B_*Nn)      // 50176

// ---------------------------------------------------------------------------
// Scratch (__device__ globals; no allocations allowed)
// ---------------------------------------------------------------------------
__device__ float g_qkv[(size_t)M_ROWS * C3];   // fp32 q|k|v
__device__ float g_y  [(size_t)M_ROWS * C_];   // attn out + LIM (fp32)

// ---------------------------------------------------------------------------
// mma.sync helpers
// ---------------------------------------------------------------------------
__device__ __forceinline__ uint32_t smaddr(const void* p) {
    return (uint32_t)__cvta_generic_to_shared(p);
}
__device__ __forceinline__ void ldsm4(uint32_t* r, uint32_t addr) {
    asm volatile("ldmatrix.sync.aligned.m8n8.x4.shared.b16 {%0,%1,%2,%3}, [%4];\n"
                 : "=r"(r[0]), "=r"(r[1]), "=r"(r[2]), "=r"(r[3]) : "r"(addr));
}
__device__ __forceinline__ void ldsm4t(uint32_t* r, uint32_t addr) {
    asm volatile("ldmatrix.sync.aligned.m8n8.x4.trans.shared.b16 {%0,%1,%2,%3}, [%4];\n"
                 : "=r"(r[0]), "=r"(r[1]), "=r"(r[2]), "=r"(r[3]) : "r"(addr));
}
__device__ __forceinline__ void mma_bf16(float* c, const uint32_t* a,
                                         uint32_t b0, uint32_t b1) {
    asm volatile(
        "mma.sync.aligned.m16n8k16.row.col.f32.bf16.bf16.f32 "
        "{%0,%1,%2,%3}, {%4,%5,%6,%7}, {%8,%9}, {%0,%1,%2,%3};\n"
        : "+f"(c[0]), "+f"(c[1]), "+f"(c[2]), "+f"(c[3])
        : "r"(a[0]), "r"(a[1]), "r"(a[2]), "r"(a[3]), "r"(b0), "r"(b1));
}

// pack 4 floats -> 4 bf16 hi (uint2) and 4 bf16 lo (uint2)
__device__ __forceinline__ void split4(float4 v, uint2& h, uint2& l) {
    union { __nv_bfloat16 b[4]; uint2 u; } hu, lu;
    float f[4] = {v.x, v.y, v.z, v.w};
#pragma unroll
    for (int j = 0; j < 4; j++) {
        __nv_bfloat16 hb = __float2bfloat16(f[j]);
        hu.b[j] = hb;
        lu.b[j] = __float2bfloat16(f[j] - __bfloat162float(hb));
    }
    h = hu.u; l = lu.u;
}

// ---------------------------------------------------------------------------
// Fused-split bf16 GEMM: C[M,N] = A_f32[M,K] @ B_f32[K,N] (+ bias)
// In-register fp32 -> bf16 hi/lo split; 3-term mma (Ah*Bh + Al*Bh + Ah*Bl).
// Block tile 128x128x32, 8 warps, warp tile 32x64, double-buffered smem.
// M%128==0, N%128==0, K%32==0.
// ---------------------------------------------------------------------------
__global__ __launch_bounds__(256)
void bmma_gemm(const float* __restrict__ A, const float* __restrict__ B,
               float* __restrict__ C, int M, int N, int K,
               const float* __restrict__ bias)
{
    __shared__ __align__(16) __nv_bfloat16 sAh[2][128][40];
    __shared__ __align__(16) __nv_bfloat16 sAl[2][128][40];
    __shared__ __align__(16) __nv_bfloat16 sBh[2][32][136];
    __shared__ __align__(16) __nv_bfloat16 sBl[2][32][136];

    const int tid  = threadIdx.x;
    const int lane = tid & 31;
    const int warp = tid >> 5;
    const int wm = (warp & 3) * 32;   // warp row offset
    const int wn = (warp >> 2) * 64;  // warp col offset
    const int bx = blockIdx.x, by = blockIdx.y;

    const float* Ag = A + (size_t)by * 128 * K;
    const float* Bg = B + (size_t)bx * 128;

    // A tile: 128x32 fp32 -> 1024 float4 segs; seg: row=seg>>3, col=(seg&7)*4
    // B tile: 32x128 fp32 -> 1024 float4 segs; seg: row=seg>>5, col=(seg&31)*4
    float4 ra[4], rb[4];
    const int ntiles = K / 32;

    auto load_tile = [&](int k0) {
#pragma unroll
        for (int i = 0; i < 4; i++) {
            int seg = tid + i * 256;
            int ar = seg >> 3, ac = (seg & 7) * 4;
            ra[i] = *reinterpret_cast<const float4*>(Ag + (size_t)ar * K + k0 + ac);
            int br = seg >> 5, bc = (seg & 31) * 4;
            rb[i] = *reinterpret_cast<const float4*>(Bg + (size_t)(k0 + br) * N + bc);
        }
    };
    auto store_tile = [&](int buf) {
#pragma unroll
        for (int i = 0; i < 4; i++) {
            int seg = tid + i * 256;
            int ar = seg >> 3, ac = (seg & 7) * 4;
            uint2 h, l;
            split4(ra[i], h, l);
            *reinterpret_cast<uint2*>(&sAh[buf][ar][ac]) = h;
            *reinterpret_cast<uint2*>(&sAl[buf][ar][ac]) = l;
            int br = seg >> 5, bc = (seg & 31) * 4;
            split4(rb[i], h, l);
            *reinterpret_cast<uint2*>(&sBh[buf][br][bc]) = h;
            *reinterpret_cast<uint2*>(&sBl[buf][br][bc]) = l;
        }
    };

    float acc[2][8][4];
#pragma unroll
    for (int mt = 0; mt < 2; mt++)
#pragma unroll
        for (int nt = 0; nt < 8; nt++)
#pragma unroll
            for (int j = 0; j < 4; j++) acc[mt][nt][j] = 0.f;

    load_tile(0);
    store_tile(0);
    __syncthreads();

    for (int kt = 0; kt < ntiles; kt++) {
        const int buf = kt & 1;
        // prefetch next tile (gmem latency overlaps compute below)
        if (kt + 1 < ntiles) load_tile((kt + 1) * 32);

#pragma unroll
        for (int ks = 0; ks < 2; ks++) {
            const int kk = ks * 16;
            uint32_t ah[2][4], al[2][4];
#pragma unroll
            for (int mt = 0; mt < 2; mt++) {
                int row = wm + mt * 16 + (lane & 15);
                int col = kk + ((lane >> 4) << 3);
                ldsm4(ah[mt], smaddr(&sAh[buf][row][col]));
                ldsm4(al[mt], smaddr(&sAl[buf][row][col]));
            }
            uint32_t bh[4][4], bl[4][4];
#pragma unroll
            for (int nt = 0; nt < 4; nt++) {
                int row = kk + (lane & 15);
                int col = wn + nt * 16 + ((lane >> 4) << 3);
                ldsm4t(bh[nt], smaddr(&sBh[buf][row][col]));
                ldsm4t(bl[nt], smaddr(&sBl[buf][row][col]));
            }
#pragma unroll
            for (int mt = 0; mt < 2; mt++)
#pragma unroll
                for (int nt = 0; nt < 8; nt++) {
                    uint32_t h0 = bh[nt >> 1][(nt & 1) * 2];
                    uint32_t h1 = bh[nt >> 1][(nt & 1) * 2 + 1];
                    uint32_t l0 = bl[nt >> 1][(nt & 1) * 2];
                    uint32_t l1 = bl[nt >> 1][(nt & 1) * 2 + 1];
                    mma_bf16(acc[mt][nt], ah[mt], h0, h1);   // Ah*Bh
                    mma_bf16(acc[mt][nt], al[mt], h0, h1);   // Al*Bh
                    mma_bf16(acc[mt][nt], ah[mt], l0, l1);   // Ah*Bl
                }
        }

        if (kt + 1 < ntiles) {
            store_tile(1 - buf);   // write other buffer; current still being read is fine
            __syncthreads();
        }
    }

#pragma unroll
    for (int mt = 0; mt < 2; mt++) {
        int r0 = by * 128 + wm + mt * 16 + (lane >> 2);
#pragma unroll
        for (int nt = 0; nt < 8; nt++) {
            int c0 = bx * 128 + wn + nt * 8 + (lane & 3) * 2;
            float bb0 = bias ? bias[c0] : 0.f;
            float bb1 = bias ? bias[c0 + 1] : 0.f;
            float2 v0 = {acc[mt][nt][0] + bb0, acc[mt][nt][1] + bb1};
            float2 v1 = {acc[mt][nt][2] + bb0, acc[mt][nt][3] + bb1};
            *reinterpret_cast<float2*>(&C[(size_t)r0 * N + c0]) = v0;
            *reinterpret_cast<float2*>(&C[(size_t)(r0 + 8) * N + c0]) = v1;
        }
    }
}

// ---------------------------------------------------------------------------
// Window attention: one block per (batch, window, head), 64 threads.
// All head slices are 32-float (128B) aligned -> float4 everywhere.
// ---------------------------------------------------------------------------
__global__ __launch_bounds__(64)
void attn_kernel(const float* __restrict__ qkv, float* __restrict__ y)
{
    int blk  = blockIdx.x;
    int head = blk % HEADS_;
    int w    = (blk / HEADS_) % NW;
    int b    = blk / (HEADS_ * NW);
    int wy = w / WG, wx = w % WG;

    __shared__ float ks[WT][HD];
    __shared__ float vs[WT][HD];

    int tid = threadIdx.x;
    // 49 rows x 8 float4 per row = 392 segs per array
    for (int idx = tid; idx < WT * (HD / 4); idx += 64) {
        int j = idx >> 3, d4 = (idx & 7) * 4;
        int n = (wy * WS_ + j / WS_) * Ww + wx * WS_ + (j % WS_);
        size_t base = ((size_t)b * Nn + n) * C3 + head * HD + d4;
        *reinterpret_cast<float4*>(&ks[j][d4]) =
            *reinterpret_cast<const float4*>(qkv + base + C_);
        *reinterpret_cast<float4*>(&vs[j][d4]) =
            *reinterpret_cast<const float4*>(qkv + base + 2 * C_);
    }
    __syncthreads();

    if (tid >= WT) return;
    int n = (wy * WS_ + tid / WS_) * Ww + wx * WS_ + (tid % WS_);
    const float* qp = qkv + ((size_t)b * Nn + n) * C3 + head * HD;

    float q[HD];
#pragma unroll
    for (int d4 = 0; d4 < HD; d4 += 4) {
        float4 v = *reinterpret_cast<const float4*>(qp + d4);
        q[d4] = v.x; q[d4 + 1] = v.y; q[d4 + 2] = v.z; q[d4 + 3] = v.w;
    }

    const float scale = 0.1767766952966369f;
    float s[WT];
    float mx = -1e30f;
#pragma unroll 7
    for (int j = 0; j < WT; j++) {
        float acc = 0.f;
#pragma unroll
        for (int d = 0; d < HD; d++) acc = fmaf(q[d], ks[j][d], acc);
        acc *= scale;
        s[j] = acc;
        mx = fmaxf(mx, acc);
    }
    float sum = 0.f;
#pragma unroll 7
    for (int j = 0; j < WT; j++) { s[j] = __expf(s[j] - mx); sum += s[j]; }
    float inv = 1.f / sum;

    float o[HD];
#pragma unroll
    for (int d = 0; d < HD; d++) o[d] = 0.f;
#pragma unroll 7
    for (int j = 0; j < WT; j++) {
        float p = s[j];
#pragma unroll
        for (int d = 0; d < HD; d++) o[d] = fmaf(p, vs[j][d], o[d]);
    }

    float* yp = y + ((size_t)b * Nn + n) * C_ + head * HD;
#pragma unroll
    for (int d4 = 0; d4 < HD; d4 += 4) {
        float4 v = {o[d4] * inv, o[d4 + 1] * inv, o[d4 + 2] * inv, o[d4 + 3] * inv};
        *reinterpret_cast<float4*>(yp + d4) = v;
    }
}

// ---------------------------------------------------------------------------
// Depthwise 3x3 conv (SAME) over v, accumulated into y. float4 over channels.
// ---------------------------------------------------------------------------
__global__ __launch_bounds__(256)
void conv_add_kernel(const float* __restrict__ qkv, const float* __restrict__ wconv,
                     const float* __restrict__ bconv, float* __restrict__ y)
{
    const int C4 = C_ / 4;
    long long idx = (long long)blockIdx.x * blockDim.x + threadIdx.x;
    if (idx >= (long long)B_ * Nn * C4) return;
    int c4 = (int)(idx % C4);
    int n  = (int)((idx / C4) % Nn);
    int b  = (int)(idx / ((long long)C4 * Nn));
    int h = n / Ww, w = n % Ww;
    int c = c4 * 4;

    float4 acc = *reinterpret_cast<const float4*>(bconv + c);
#pragma unroll
    for (int ky = 0; ky < 3; ky++) {
        int hy = h + ky - 1;
        if (hy < 0 || hy >= Hh) continue;
#pragma unroll
        for (int kx = 0; kx < 3; kx++) {
            int wx2 = w + kx - 1;
            if (wx2 < 0 || wx2 >= Ww) continue;
            float4 vv = *reinterpret_cast<const float4*>(
                qkv + ((size_t)b * Nn + hy * Ww + wx2) * C3 + 2 * C_ + c);
            float4 wc = *reinterpret_cast<const float4*>(
                wconv + (ky * 3 + kx) * C_ + c);
            acc.x = fmaf(vv.x, wc.x, acc.x);
            acc.y = fmaf(vv.y, wc.y, acc.y);
            acc.z = fmaf(vv.z, wc.z, acc.z);
            acc.w = fmaf(vv.w, wc.w, acc.w);
        }
    }
    float4* yp = reinterpret_cast<float4*>(y + ((size_t)b * Nn + n) * C_ + c);
    float4 old = *yp;
    old.x += acc.x; old.y += acc.y; old.z += acc.z; old.w += acc.w;
    *yp = old;
}

// ---------------------------------------------------------------------------
// Launch
// ---------------------------------------------------------------------------
extern "C" void kernel_launch(void* const* d_in, const int* in_sizes, int n_in,
                              void* d_out, int out_size)
{
    const float* x      = (const float*)d_in[0];
    const float* w_qkv  = (const float*)d_in[1];
    const float* w_proj = (const float*)d_in[2];
    const float* b_proj = (const float*)d_in[3];
    const float* w_conv = (const float*)d_in[4];
    const float* b_conv = (const float*)d_in[5];
    float* out = (float*)d_out;

    float *qkv, *y;
    cudaGetSymbolAddress((void**)&qkv, g_qkv);
    cudaGetSymbolAddress((void**)&y,   g_y);

    // 1) QKV GEMM (fused split, tensor cores): (50176,384) @ (384,1152)
    {
        dim3 grid(C3 / 128, M_ROWS / 128);
        bmma_gemm<<<grid, 256>>>(x, w_qkv, qkv, M_ROWS, C3, C_, nullptr);
    }
    // 2) window attention -> y
    attn_kernel<<<B_ * NW * HEADS_, 64>>>(qkv, y);
    // 3) depthwise conv, += into y
    {
        long long total = (long long)B_ * Nn * (C_ / 4);
        conv_add_kernel<<<(unsigned)((total + 255) / 256), 256>>>(qkv, w_conv, b_conv, y);
    }
    // 4) proj GEMM + bias -> out
    {
        dim3 grid(C_ / 128, M_ROWS / 128);
        bmma_gemm<<<grid, 256>>>(y, w_proj, out, M_ROWS, C_, C_, b_proj);
    }
}